// round 2
// baseline (speedup 1.0000x reference)
#include <cuda_runtime.h>
#include <cuda_bf16.h>
#include <math.h>

// Problem constants: B=2, L=512 (both sides), Dh=1024, P=64, C = 4P+1 = 257
#define NB    2
#define LSEQ  512
#define DH    1024
#define PP    64
#define NCH   257
#define PLANE (LSEQ*LSEQ)      // 262144 floats per channel plane
#define PLANE4 (PLANE/4)       // 65536 float4
#define NROWS (NB*LSEQ)        // 1024 rows per side

// Scratch (device globals; no allocation allowed)
__device__ float g_part[4 * 2 * NROWS * PP]; // [kc][side][row][p] partial GEMM sums
__device__ float g_za [NROWS*PP];            // side a: [b*512+i][p] row-major
__device__ float g_zbr[NROWS*PP];            // side b: [b*512+j][p] row-major
__device__ float g_zbT[NB*PP*LSEQ];          // side b: [b][p][j] transposed
__device__ float g_na [NROWS];
__device__ float g_nb [NROWS];

__device__ __forceinline__ float gelu_exact(float x) {
    return 0.5f * x * (1.0f + erff(x * 0.7071067811865476f));
}

// ---------------------------------------------------------------------------
// Kernel A1: partial projection GEMM over a 256-wide K chunk.
// grid (128 rowgroups, 2 sides, 4 kchunks), block (16,8).
// tx = p-quad (4 consecutive p), ty = row within 8-row tile.
// ---------------------------------------------------------------------------
__global__ __launch_bounds__(128) void proj_partial(
    const float* __restrict__ h_a, const float* __restrict__ h_b,
    const float* __restrict__ Wa,  const float* __restrict__ Wb)
{
    const int side = blockIdx.y;
    const int kc   = blockIdx.z;                 // 0..3
    const float* __restrict__ H  = side ? h_b : h_a;
    const float* __restrict__ Wp = side ? Wb  : Wa;

    const int tx = threadIdx.x;                  // 0..15
    const int ty = threadIdx.y;                  // 0..7
    const int tid = ty * 16 + tx;
    const int rowBase = blockIdx.x * 8;

    // h chunk: 8 rows x 256 floats, float4 pitch 65 (pad)
    __shared__ float h_s[8 * 260];
    {
        const float4* __restrict__ H4 = (const float4*)H;
        float4* hs4 = (float4*)h_s;
        const int k0_4 = kc * 64;
        #pragma unroll
        for (int it = 0; it < 4; ++it) {
            int idx = tid + it * 128;            // 0..511
            int r   = idx >> 6;                  // row in tile
            int c4  = idx & 63;                  // float4 col in chunk
            hs4[r * 65 + c4] = H4[(size_t)(rowBase + r) * 256 + k0_4 + c4];
        }
    }
    __syncthreads();

    const float4* __restrict__ W4 = (const float4*)Wp;   // [1024][16] float4
    const float4* hrow = ((const float4*)h_s) + ty * 65;
    const int kbase = kc * 256;

    float4 acc = make_float4(0.f, 0.f, 0.f, 0.f);
    #pragma unroll 4
    for (int k4 = 0; k4 < 64; ++k4) {
        float4 h4 = hrow[k4];
        int k = kbase + 4 * k4;
        float4 w0 = W4[(k + 0) * 16 + tx];
        float4 w1 = W4[(k + 1) * 16 + tx];
        float4 w2 = W4[(k + 2) * 16 + tx];
        float4 w3 = W4[(k + 3) * 16 + tx];
        acc.x += h4.x*w0.x; acc.y += h4.x*w0.y; acc.z += h4.x*w0.z; acc.w += h4.x*w0.w;
        acc.x += h4.y*w1.x; acc.y += h4.y*w1.y; acc.z += h4.y*w1.z; acc.w += h4.y*w1.w;
        acc.x += h4.z*w2.x; acc.y += h4.z*w2.y; acc.z += h4.z*w2.z; acc.w += h4.z*w2.w;
        acc.x += h4.w*w3.x; acc.y += h4.w*w3.y; acc.z += h4.w*w3.z; acc.w += h4.w*w3.w;
    }

    const int row = rowBase + ty;  // 0..1023 (includes b)
    ((float4*)g_part)[(((size_t)kc * 2 + side) * NROWS + row) * 16 + tx] = acc;
}

// ---------------------------------------------------------------------------
// Kernel A2: reduce 4 partials, bias + exact GELU, per-row norm, layout writes.
// grid (128, 2), block (16,8).
// ---------------------------------------------------------------------------
__global__ __launch_bounds__(128) void reduce_gelu(
    const float* __restrict__ ba, const float* __restrict__ bb)
{
    const int side = blockIdx.y;
    const float* __restrict__ bp = side ? bb : ba;
    const int tx = threadIdx.x;
    const int ty = threadIdx.y;
    const int row = blockIdx.x * 8 + ty;

    const float4* P4 = (const float4*)g_part;
    float4 a0 = P4[(((size_t)0 * 2 + side) * NROWS + row) * 16 + tx];
    float4 a1 = P4[(((size_t)1 * 2 + side) * NROWS + row) * 16 + tx];
    float4 a2 = P4[(((size_t)2 * 2 + side) * NROWS + row) * 16 + tx];
    float4 a3 = P4[(((size_t)3 * 2 + side) * NROWS + row) * 16 + tx];
    const float4 bias4 = ((const float4*)bp)[tx];

    float4 z;
    z.x = gelu_exact(a0.x + a1.x + a2.x + a3.x + bias4.x);
    z.y = gelu_exact(a0.y + a1.y + a2.y + a3.y + bias4.y);
    z.z = gelu_exact(a0.z + a1.z + a2.z + a3.z + bias4.z);
    z.w = gelu_exact(a0.w + a1.w + a2.w + a3.w + bias4.w);

    float ss = z.x*z.x + z.y*z.y + z.z*z.z + z.w*z.w;
    ss += __shfl_xor_sync(0xFFFFFFFFu, ss, 1, 16);
    ss += __shfl_xor_sync(0xFFFFFFFFu, ss, 2, 16);
    ss += __shfl_xor_sync(0xFFFFFFFFu, ss, 4, 16);
    ss += __shfl_xor_sync(0xFFFFFFFFu, ss, 8, 16);

    if (side == 0) {
        ((float4*)g_za)[(size_t)row * 16 + tx] = z;
        if (tx == 0) g_na[row] = sqrtf(ss + 1e-8f);
    } else {
        ((float4*)g_zbr)[(size_t)row * 16 + tx] = z;
        const int b = row >> 9;
        const int j = row & 511;
        const int p0 = tx * 4;
        float* dst = g_zbT + ((size_t)(b * PP + p0)) * LSEQ + j;
        dst[0*LSEQ] = z.x;
        dst[1*LSEQ] = z.y;
        dst[2*LSEQ] = z.z;
        dst[3*LSEQ] = z.w;
        if (tx == 0) g_nb[row] = sqrtf(ss + 1e-8f);
    }
}

// ---------------------------------------------------------------------------
// Kernel C: cosine-sim plane via a 64x64-tile register GEMM over K=P=64.
// grid (8 i-tiles, 8 j-tiles, 2), block 256, 4x4 outputs/thread.
// ---------------------------------------------------------------------------
__global__ __launch_bounds__(256) void sim_kernel(float* __restrict__ out)
{
    const int bi = blockIdx.x, bj = blockIdx.y, b = blockIdx.z;
    const int t = threadIdx.x;

    __shared__ float za_s[64 * 65];   // [i][p], pitch 65
    __shared__ float zb_s[64 * 65];   // [j][p], pitch 65

    // Cooperative load: 64 rows x 16 float4 each, scalar-scatter into padded smem
    #pragma unroll
    for (int it = 0; it < 4; ++it) {
        int idx = t + it * 256;              // 0..1023 float4 slots
        int r   = idx >> 4;                  // row
        int c4  = idx & 15;                  // float4 col
        float4 va = ((const float4*)g_za )[((size_t)(b * LSEQ + bi * 64 + r)) * 16 + c4];
        float4 vb = ((const float4*)g_zbr)[((size_t)(b * LSEQ + bj * 64 + r)) * 16 + c4];
        float* da = &za_s[r * 65 + c4 * 4];
        float* db = &zb_s[r * 65 + c4 * 4];
        da[0]=va.x; da[1]=va.y; da[2]=va.z; da[3]=va.w;
        db[0]=vb.x; db[1]=vb.y; db[2]=vb.z; db[3]=vb.w;
    }
    __syncthreads();

    const int ti = t >> 4;    // 0..15
    const int tj = t & 15;    // 0..15

    float acc[4][4];
    #pragma unroll
    for (int r = 0; r < 4; ++r)
        #pragma unroll
        for (int c = 0; c < 4; ++c) acc[r][c] = 0.f;

    #pragma unroll 8
    for (int p = 0; p < 64; ++p) {
        float av[4], bv[4];
        #pragma unroll
        for (int r = 0; r < 4; ++r) av[r] = za_s[(ti * 4 + r) * 65 + p];
        #pragma unroll
        for (int c = 0; c < 4; ++c) bv[c] = zb_s[(tj * 4 + c) * 65 + p];
        #pragma unroll
        for (int r = 0; r < 4; ++r)
            #pragma unroll
            for (int c = 0; c < 4; ++c)
                acc[r][c] += av[r] * bv[c];
    }

    float inb[4];
    #pragma unroll
    for (int c = 0; c < 4; ++c)
        inb[c] = 1.0f / g_nb[b * LSEQ + bj * 64 + tj * 4 + c];

    float* Os = out + ((size_t)b * NCH + 256) * PLANE;
    #pragma unroll
    for (int r = 0; r < 4; ++r) {
        const int i = bi * 64 + ti * 4 + r;
        const float ina = 1.0f / g_na[b * LSEQ + i];
        float4 s;
        s.x = acc[r][0] * ina * inb[0];
        s.y = acc[r][1] * ina * inb[1];
        s.z = acc[r][2] * ina * inb[2];
        s.w = acc[r][3] * ina * inb[3];
        __stcs((float4*)(Os + (size_t)i * LSEQ + bj * 64 + tj * 4), s);
    }
}

// ---------------------------------------------------------------------------
// Kernel B: the 4 broadcast channel groups (za, zb, |diff|, prod).
// grid (512 i, 2 b, 4 p-chunks), block 128; each block: 16 p x full j row.
// Pure streaming: 1 LDG.128 + 4 STG.128 (streaming) per p-iteration.
// ---------------------------------------------------------------------------
__global__ __launch_bounds__(128) void interact_kernel(float* __restrict__ out)
{
    const int i  = blockIdx.x;
    const int b  = blockIdx.y;
    const int pc = blockIdx.z;      // 0..3 (16 channels each)
    const int t  = threadIdx.x;     // j = 4t..4t+3

    __shared__ float za_s[16];
    if (t < 16) za_s[t] = g_za[((size_t)(b * LSEQ + i)) * PP + pc * 16 + t];
    __syncthreads();

    const float4* ZBT = ((const float4*)(g_zbT + ((size_t)b * PP + pc * 16) * LSEQ)) + t;
    float4* O = ((float4*)out) + (size_t)(b * NCH + pc * 16) * PLANE4
                               + (size_t)i * (LSEQ/4) + t;

    #pragma unroll
    for (int p = 0; p < 16; ++p) {
        float4 zb = __ldg(ZBT + p * (LSEQ/4));
        float  za = za_s[p];
        float4* o = O + (size_t)p * PLANE4;

        __stcs(o,                          make_float4(za, za, za, za));
        __stcs(o + (size_t) 64 * PLANE4,   zb);
        __stcs(o + (size_t)128 * PLANE4,
               make_float4(fabsf(za - zb.x), fabsf(za - zb.y),
                           fabsf(za - zb.z), fabsf(za - zb.w)));
        __stcs(o + (size_t)192 * PLANE4,
               make_float4(za * zb.x, za * zb.y, za * zb.z, za * zb.w));
    }
}

extern "C" void kernel_launch(void* const* d_in, const int* in_sizes, int n_in,
                              void* d_out, int out_size)
{
    const float* h_a = (const float*)d_in[0];
    const float* h_b = (const float*)d_in[1];
    const float* Wa  = (const float*)d_in[2];
    const float* ba  = (const float*)d_in[3];
    const float* Wb  = (const float*)d_in[4];
    const float* bb  = (const float*)d_in[5];
    float* out = (float*)d_out;

    proj_partial<<<dim3(128, 2, 4), dim3(16, 8)>>>(h_a, h_b, Wa, Wb);
    reduce_gelu <<<dim3(128, 2),    dim3(16, 8)>>>(ba, bb);
    sim_kernel  <<<dim3(8, 8, 2),   256>>>(out);
    interact_kernel<<<dim3(512, 2, 4), 128>>>(out);
}

// round 3
// speedup vs baseline: 1.0143x; 1.0143x over previous
#include <cuda_runtime.h>
#include <cuda_bf16.h>
#include <math.h>

// Problem constants: B=2, L=512 (both sides), Dh=1024, P=64, C = 4P+1 = 257
#define NB    2
#define LSEQ  512
#define DH    1024
#define PP    64
#define NCH   257
#define PLANE (LSEQ*LSEQ)      // 262144 floats per channel plane
#define PLANE4 (PLANE/4)
#define NROWS (NB*LSEQ)        // 1024 rows per side
#define NKC   8                // K chunks in projection

// Scratch (device globals; no allocation allowed)
__device__ float g_part[NKC * 2 * NROWS * PP]; // [kc][side][row][p]
__device__ float g_za [NROWS*PP];              // side a: [b*512+i][p]
__device__ float g_zbr[NROWS*PP];              // side b: [b*512+j][p]
__device__ float g_zbT[NB*PP*LSEQ];            // side b: [b][p][j]
__device__ float g_na [NROWS];
__device__ float g_nb [NROWS];

__device__ __forceinline__ float gelu_exact(float x) {
    return 0.5f * x * (1.0f + erff(x * 0.7071067811865476f));
}

// ---------------------------------------------------------------------------
// Kernel A1: partial projection over a 128-wide K chunk, W chunk staged in
// smem (kills L2-latency dependence). grid (64 rowgroups, 2 sides, 8 kc),
// block 256: tx = p-quad (0..15), ty = row (0..15).
// ---------------------------------------------------------------------------
__global__ __launch_bounds__(256) void proj_partial(
    const float* __restrict__ h_a, const float* __restrict__ h_b,
    const float* __restrict__ Wa,  const float* __restrict__ Wb)
{
    const int side = blockIdx.y;
    const int kc   = blockIdx.z;                 // 0..7, K chunk of 128
    const float* __restrict__ H  = side ? h_b : h_a;
    const float* __restrict__ Wp = side ? Wb  : Wa;

    const int tid = threadIdx.x;
    const int tx = tid & 15;                     // p-quad
    const int ty = tid >> 4;                     // row 0..15
    const int rowBase = blockIdx.x * 16;

    __shared__ float4 w_s[128 * 16];             // [k][p4] 32KB
    __shared__ float4 h_s[16 * 33];              // [row][k4] padded pitch 33

    // W chunk: 128 k x 16 float4 = 2048 float4, 8 per thread (coalesced)
    {
        const float4* __restrict__ W4 = (const float4*)Wp;  // [1024][16]
        #pragma unroll
        for (int it = 0; it < 8; ++it) {
            int idx = tid + it * 256;            // 0..2047
            int k   = idx >> 4;
            int p4  = idx & 15;
            w_s[idx] = W4[(size_t)(kc * 128 + k) * 16 + p4];
        }
    }
    // h tile: 16 rows x 32 float4 = 512 float4, 2 per thread
    {
        const float4* __restrict__ H4 = (const float4*)H;   // [row][256]
        #pragma unroll
        for (int it = 0; it < 2; ++it) {
            int idx = tid + it * 256;            // 0..511
            int r   = idx >> 5;
            int c   = idx & 31;
            h_s[r * 33 + c] = H4[(size_t)(rowBase + r) * 256 + kc * 32 + c];
        }
    }
    __syncthreads();

    const float4* hrow = h_s + ty * 33;
    float4 acc = make_float4(0.f, 0.f, 0.f, 0.f);

    #pragma unroll 8
    for (int k4 = 0; k4 < 32; ++k4) {
        float4 h4 = hrow[k4];
        const float4* wk = w_s + (4 * k4) * 16 + tx;
        float4 w0 = wk[0], w1 = wk[16], w2 = wk[32], w3 = wk[48];
        acc.x += h4.x*w0.x; acc.y += h4.x*w0.y; acc.z += h4.x*w0.z; acc.w += h4.x*w0.w;
        acc.x += h4.y*w1.x; acc.y += h4.y*w1.y; acc.z += h4.y*w1.z; acc.w += h4.y*w1.w;
        acc.x += h4.z*w2.x; acc.y += h4.z*w2.y; acc.z += h4.z*w2.z; acc.w += h4.z*w2.w;
        acc.x += h4.w*w3.x; acc.y += h4.w*w3.y; acc.z += h4.w*w3.z; acc.w += h4.w*w3.w;
    }

    const int row = rowBase + ty;
    ((float4*)g_part)[(((size_t)kc * 2 + side) * NROWS + row) * 16 + tx] = acc;
}

// ---------------------------------------------------------------------------
// Kernel A2: reduce 8 partials, bias + exact GELU, per-row norm, layouts.
// grid (128, 2), block (16,8).
// ---------------------------------------------------------------------------
__global__ __launch_bounds__(128) void reduce_gelu(
    const float* __restrict__ ba, const float* __restrict__ bb)
{
    const int side = blockIdx.y;
    const float* __restrict__ bp = side ? bb : ba;
    const int tx = threadIdx.x;
    const int ty = threadIdx.y;
    const int row = blockIdx.x * 8 + ty;

    const float4* P4 = (const float4*)g_part;
    float4 a = P4[(((size_t)0 * 2 + side) * NROWS + row) * 16 + tx];
    #pragma unroll
    for (int c = 1; c < NKC; ++c) {
        float4 v = P4[(((size_t)c * 2 + side) * NROWS + row) * 16 + tx];
        a.x += v.x; a.y += v.y; a.z += v.z; a.w += v.w;
    }
    const float4 bias4 = ((const float4*)bp)[tx];

    float4 z;
    z.x = gelu_exact(a.x + bias4.x);
    z.y = gelu_exact(a.y + bias4.y);
    z.z = gelu_exact(a.z + bias4.z);
    z.w = gelu_exact(a.w + bias4.w);

    float ss = z.x*z.x + z.y*z.y + z.z*z.z + z.w*z.w;
    ss += __shfl_xor_sync(0xFFFFFFFFu, ss, 1, 16);
    ss += __shfl_xor_sync(0xFFFFFFFFu, ss, 2, 16);
    ss += __shfl_xor_sync(0xFFFFFFFFu, ss, 4, 16);
    ss += __shfl_xor_sync(0xFFFFFFFFu, ss, 8, 16);

    if (side == 0) {
        ((float4*)g_za)[(size_t)row * 16 + tx] = z;
        if (tx == 0) g_na[row] = sqrtf(ss + 1e-8f);
    } else {
        ((float4*)g_zbr)[(size_t)row * 16 + tx] = z;
        const int b = row >> 9;
        const int j = row & 511;
        const int p0 = tx * 4;
        float* dst = g_zbT + ((size_t)(b * PP + p0)) * LSEQ + j;
        dst[0*LSEQ] = z.x;
        dst[1*LSEQ] = z.y;
        dst[2*LSEQ] = z.z;
        dst[3*LSEQ] = z.w;
        if (tx == 0) g_nb[row] = sqrtf(ss + 1e-8f);
    }
}

// ---------------------------------------------------------------------------
// Kernel C: cosine-sim plane via 64x64-tile register GEMM over K=P=64.
// grid (8, 8, 2), block 256, 4x4 outputs/thread.
// ---------------------------------------------------------------------------
__global__ __launch_bounds__(256) void sim_kernel(float* __restrict__ out)
{
    const int bi = blockIdx.x, bj = blockIdx.y, b = blockIdx.z;
    const int t = threadIdx.x;

    __shared__ float za_s[64 * 65];
    __shared__ float zb_s[64 * 65];

    #pragma unroll
    for (int it = 0; it < 4; ++it) {
        int idx = t + it * 256;
        int r   = idx >> 4;
        int c4  = idx & 15;
        float4 va = ((const float4*)g_za )[((size_t)(b * LSEQ + bi * 64 + r)) * 16 + c4];
        float4 vb = ((const float4*)g_zbr)[((size_t)(b * LSEQ + bj * 64 + r)) * 16 + c4];
        float* da = &za_s[r * 65 + c4 * 4];
        float* db = &zb_s[r * 65 + c4 * 4];
        da[0]=va.x; da[1]=va.y; da[2]=va.z; da[3]=va.w;
        db[0]=vb.x; db[1]=vb.y; db[2]=vb.z; db[3]=vb.w;
    }
    __syncthreads();

    const int ti = t >> 4;
    const int tj = t & 15;

    float acc[4][4];
    #pragma unroll
    for (int r = 0; r < 4; ++r)
        #pragma unroll
        for (int c = 0; c < 4; ++c) acc[r][c] = 0.f;

    #pragma unroll 8
    for (int p = 0; p < 64; ++p) {
        float av[4], bv[4];
        #pragma unroll
        for (int r = 0; r < 4; ++r) av[r] = za_s[(ti * 4 + r) * 65 + p];
        #pragma unroll
        for (int c = 0; c < 4; ++c) bv[c] = zb_s[(tj * 4 + c) * 65 + p];
        #pragma unroll
        for (int r = 0; r < 4; ++r)
            #pragma unroll
            for (int c = 0; c < 4; ++c)
                acc[r][c] += av[r] * bv[c];
    }

    float inb[4];
    #pragma unroll
    for (int c = 0; c < 4; ++c)
        inb[c] = 1.0f / g_nb[b * LSEQ + bj * 64 + tj * 4 + c];

    float* Os = out + ((size_t)b * NCH + 256) * PLANE;
    #pragma unroll
    for (int r = 0; r < 4; ++r) {
        const int i = bi * 64 + ti * 4 + r;
        const float ina = 1.0f / g_na[b * LSEQ + i];
        float4 s;
        s.x = acc[r][0] * ina * inb[0];
        s.y = acc[r][1] * ina * inb[1];
        s.z = acc[r][2] * ina * inb[2];
        s.w = acc[r][3] * ina * inb[3];
        __stcs((float4*)(Os + (size_t)i * LSEQ + bj * 64 + tj * 4), s);
    }
}

// ---------------------------------------------------------------------------
// Kernel B: broadcast channels. ONE contiguous 128KB stream per block:
// block = (b, group, p, i-chunk of 64 rows), writes 64 consecutive rows of a
// single plane. grid (8 ichunk, 64 p, 8 = group*2+b), block 128.
// ---------------------------------------------------------------------------
__global__ __launch_bounds__(128) void interact_kernel(float* __restrict__ out)
{
    const int ic = blockIdx.x;          // 0..7  (i chunk of 64)
    const int p  = blockIdx.y;          // 0..63
    const int z  = blockIdx.z;          // 0..7
    const int g  = z >> 1;              // channel group 0..3
    const int b  = z & 1;
    const int t  = threadIdx.x;         // j = 4t..4t+3

    __shared__ float za_s[64];
    if (t < 64)
        za_s[t] = g_za[((size_t)(b * LSEQ + ic * 64 + t)) * PP + p];

    const float4 zb4 = ((const float4*)(g_zbT + ((size_t)(b * PP + p)) * LSEQ))[t];
    __syncthreads();

    float* base = out + ((size_t)(b * NCH + g * PP + p)) * PLANE
                      + (size_t)(ic * 64) * LSEQ + 4 * t;

    if (g == 0) {
        #pragma unroll 8
        for (int ii = 0; ii < 64; ++ii) {
            float za = za_s[ii];
            __stcs((float4*)(base + (size_t)ii * LSEQ), make_float4(za, za, za, za));
        }
    } else if (g == 1) {
        #pragma unroll 8
        for (int ii = 0; ii < 64; ++ii)
            __stcs((float4*)(base + (size_t)ii * LSEQ), zb4);
    } else if (g == 2) {
        #pragma unroll 8
        for (int ii = 0; ii < 64; ++ii) {
            float za = za_s[ii];
            __stcs((float4*)(base + (size_t)ii * LSEQ),
                   make_float4(fabsf(za - zb4.x), fabsf(za - zb4.y),
                               fabsf(za - zb4.z), fabsf(za - zb4.w)));
        }
    } else {
        #pragma unroll 8
        for (int ii = 0; ii < 64; ++ii) {
            float za = za_s[ii];
            __stcs((float4*)(base + (size_t)ii * LSEQ),
                   make_float4(za * zb4.x, za * zb4.y, za * zb4.z, za * zb4.w));
        }
    }
}

extern "C" void kernel_launch(void* const* d_in, const int* in_sizes, int n_in,
                              void* d_out, int out_size)
{
    const float* h_a = (const float*)d_in[0];
    const float* h_b = (const float*)d_in[1];
    const float* Wa  = (const float*)d_in[2];
    const float* ba  = (const float*)d_in[3];
    const float* Wb  = (const float*)d_in[4];
    const float* bb  = (const float*)d_in[5];
    float* out = (float*)d_out;

    proj_partial<<<dim3(64, 2, NKC), 256>>>(h_a, h_b, Wa, Wb);
    reduce_gelu <<<dim3(128, 2),     dim3(16, 8)>>>(ba, bb);
    sim_kernel  <<<dim3(8, 8, 2),    256>>>(out);
    interact_kernel<<<dim3(8, 64, 8), 128>>>(out);
}

// round 5
// speedup vs baseline: 1.4781x; 1.4572x over previous
#include <cuda_runtime.h>
#include <cuda_bf16.h>
#include <math.h>

// Problem constants: B=2, L=512 (both sides), Dh=1024, P=64, C = 4P+1 = 257
#define NB    2
#define LSEQ  512
#define DH    1024
#define PP    64
#define NCH   257
#define PLANE (LSEQ*LSEQ)      // 262144 floats per channel plane
#define PLANE4 (PLANE/4)
#define NROWS (NB*LSEQ)        // 1024 rows per side
#define NKC   16               // K chunks in projection (64 wide each)
#define HPITCH 68              // h_s row pitch in floats (multiple of 4!)

// Scratch (device globals; no allocation allowed)
__device__ float g_part[NKC * 2 * NROWS * PP]; // [kc][side][row][p]  (8MB)
__device__ float g_za [NROWS*PP];              // side a: [b*512+i][p]
__device__ float g_zbT[NB*PP*LSEQ];            // side b: [b][p][j]
__device__ float g_na [NROWS];
__device__ float g_nb [NROWS];

__device__ __forceinline__ float gelu_exact(float x) {
    return 0.5f * x * (1.0f + erff(x * 0.7071067811865476f));
}

// ---------------------------------------------------------------------------
// Kernel A1: partial projection GEMM over a 64-wide K chunk.
// Register-blocked 4 rows x 4 p per thread. Block 256 threads covers a
// 64-row x 64-p tile. grid (16 rowgroups, 2 sides, 16 kchunks) = 512 blocks.
// h staged TRANSPOSED in smem ([k][row], float4-aligned pitch) so the inner
// loop is 1 LDS.128 (4 rows, 2 addrs/warp) + 1 LDS.128 (4 p) -> 16 FMA.
// ---------------------------------------------------------------------------
__global__ __launch_bounds__(256) void proj_partial(
    const float* __restrict__ h_a, const float* __restrict__ h_b,
    const float* __restrict__ Wa,  const float* __restrict__ Wb)
{
    const int side = blockIdx.y;
    const int kc   = blockIdx.z;                 // 0..15, K chunk of 64
    const float* __restrict__ H  = side ? h_b : h_a;
    const float* __restrict__ Wp = side ? Wb  : Wa;

    const int tid = threadIdx.x;
    const int tx = tid & 15;                     // p-quad 0..15
    const int ty = tid >> 4;                     // row-quad 0..15
    const int rowBase = blockIdx.x * 64;

    __shared__ float  h_s[64 * HPITCH];          // [k][row]  (~17.4KB)
    __shared__ float4 w_s[64 * 16];              // [k][p4]    (16KB)

    // Load h chunk (64 rows x 16 float4 along k) and transpose into h_s.
    {
        const float4* __restrict__ H4 = (const float4*)H;   // [row][256]
        #pragma unroll
        for (int it = 0; it < 4; ++it) {
            int idx = tid + it * 256;            // 0..1023
            int r   = idx >> 4;                  // row in tile 0..63
            int c4  = idx & 15;                  // float4 index along k
            float4 v = H4[(size_t)(rowBase + r) * 256 + kc * 16 + c4];
            h_s[(4*c4 + 0) * HPITCH + r] = v.x;
            h_s[(4*c4 + 1) * HPITCH + r] = v.y;
            h_s[(4*c4 + 2) * HPITCH + r] = v.z;
            h_s[(4*c4 + 3) * HPITCH + r] = v.w;
        }
    }
    // Load W chunk (64 k x 16 float4), coalesced, layout [k][p4].
    {
        const float4* __restrict__ W4 = (const float4*)Wp;  // [1024][16]
        #pragma unroll
        for (int it = 0; it < 4; ++it) {
            int idx = tid + it * 256;            // 0..1023
            int k   = idx >> 4;
            int p4  = idx & 15;
            w_s[idx] = W4[(size_t)(kc * 64 + k) * 16 + p4];
        }
    }
    __syncthreads();

    float4 acc0 = make_float4(0.f,0.f,0.f,0.f);
    float4 acc1 = make_float4(0.f,0.f,0.f,0.f);
    float4 acc2 = make_float4(0.f,0.f,0.f,0.f);
    float4 acc3 = make_float4(0.f,0.f,0.f,0.f);

    #pragma unroll 4
    for (int k = 0; k < 64; ++k) {
        float4 h4 = *(const float4*)&h_s[k * HPITCH + ty * 4];  // 4 rows
        float4 w4 = w_s[k * 16 + tx];                           // 4 p
        acc0.x += h4.x*w4.x; acc0.y += h4.x*w4.y; acc0.z += h4.x*w4.z; acc0.w += h4.x*w4.w;
        acc1.x += h4.y*w4.x; acc1.y += h4.y*w4.y; acc1.z += h4.y*w4.z; acc1.w += h4.y*w4.w;
        acc2.x += h4.z*w4.x; acc2.y += h4.z*w4.y; acc2.z += h4.z*w4.z; acc2.w += h4.z*w4.w;
        acc3.x += h4.w*w4.x; acc3.y += h4.w*w4.y; acc3.z += h4.w*w4.z; acc3.w += h4.w*w4.w;
    }

    float4* P4 = ((float4*)g_part) + (((size_t)kc * 2 + side) * NROWS) * 16;
    const int r0 = rowBase + ty * 4;
    P4[(size_t)(r0 + 0) * 16 + tx] = acc0;
    P4[(size_t)(r0 + 1) * 16 + tx] = acc1;
    P4[(size_t)(r0 + 2) * 16 + tx] = acc2;
    P4[(size_t)(r0 + 3) * 16 + tx] = acc3;
}

// ---------------------------------------------------------------------------
// Kernel A2: reduce 16 partials, bias + exact GELU, per-row norm, layouts.
// grid (128, 2), block (16,8).
// ---------------------------------------------------------------------------
__global__ __launch_bounds__(128) void reduce_gelu(
    const float* __restrict__ ba, const float* __restrict__ bb)
{
    const int side = blockIdx.y;
    const float* __restrict__ bp = side ? bb : ba;
    const int tx = threadIdx.x;
    const int ty = threadIdx.y;
    const int row = blockIdx.x * 8 + ty;

    const float4* P4 = (const float4*)g_part;
    float4 a = P4[(((size_t)0 * 2 + side) * NROWS + row) * 16 + tx];
    #pragma unroll
    for (int c = 1; c < NKC; ++c) {
        float4 v = P4[(((size_t)c * 2 + side) * NROWS + row) * 16 + tx];
        a.x += v.x; a.y += v.y; a.z += v.z; a.w += v.w;
    }
    const float4 bias4 = ((const float4*)bp)[tx];

    float4 z;
    z.x = gelu_exact(a.x + bias4.x);
    z.y = gelu_exact(a.y + bias4.y);
    z.z = gelu_exact(a.z + bias4.z);
    z.w = gelu_exact(a.w + bias4.w);

    float ss = z.x*z.x + z.y*z.y + z.z*z.z + z.w*z.w;
    ss += __shfl_xor_sync(0xFFFFFFFFu, ss, 1, 16);
    ss += __shfl_xor_sync(0xFFFFFFFFu, ss, 2, 16);
    ss += __shfl_xor_sync(0xFFFFFFFFu, ss, 4, 16);
    ss += __shfl_xor_sync(0xFFFFFFFFu, ss, 8, 16);

    if (side == 0) {
        ((float4*)g_za)[(size_t)row * 16 + tx] = z;
        if (tx == 0) g_na[row] = sqrtf(ss + 1e-8f);
    } else {
        const int b = row >> 9;
        const int j = row & 511;
        const int p0 = tx * 4;
        float* dst = g_zbT + ((size_t)(b * PP + p0)) * LSEQ + j;
        dst[0*LSEQ] = z.x;
        dst[1*LSEQ] = z.y;
        dst[2*LSEQ] = z.z;
        dst[3*LSEQ] = z.w;
        if (tx == 0) g_nb[row] = sqrtf(ss + 1e-8f);
    }
}

// ---------------------------------------------------------------------------
// Kernel B: full [B, 257, LA, LB] output, R1 layout (best measured: DRAM 68%).
// One block per (i, b). 128 threads, each owns 4 consecutive j. Per channel p:
// one coalesced LDG.128 of zbT row + four STG.128 streaming stores; dot for
// the cosine channel accumulated in-register; sim plane stored at the end.
// ---------------------------------------------------------------------------
__global__ __launch_bounds__(128) void interact_kernel(float* __restrict__ out)
{
    const int i = blockIdx.x;       // 0..511
    const int b = blockIdx.y;       // 0..1
    const int t = threadIdx.x;      // 0..127, covers j = 4t .. 4t+3

    __shared__ float za_s[PP];
    __shared__ float na_s;
    if (t < PP) za_s[t] = g_za[((size_t)(b * LSEQ + i)) * PP + t];
    if (t == 0) na_s = g_na[b * LSEQ + i];
    __syncthreads();

    const float4 nb4 = *(const float4*)&g_nb[b * LSEQ + 4 * t];

    float4* O = ((float4*)out) + (size_t)b * NCH * PLANE4 + (size_t)i * (LSEQ/4) + t;
    const float4* ZBT = ((const float4*)(g_zbT + (size_t)b * PP * LSEQ)) + t;

    float4 dot = make_float4(0.f, 0.f, 0.f, 0.f);

    #pragma unroll 4
    for (int p = 0; p < PP; ++p) {
        float4 zb = __ldg(ZBT + p * (LSEQ/4));
        float  za = za_s[p];
        float4* o = O + (size_t)p * PLANE4;

        __stcs(o,                          make_float4(za, za, za, za));
        __stcs(o + (size_t) 64 * PLANE4,   zb);
        __stcs(o + (size_t)128 * PLANE4,
               make_float4(fabsf(za - zb.x), fabsf(za - zb.y),
                           fabsf(za - zb.z), fabsf(za - zb.w)));
        __stcs(o + (size_t)192 * PLANE4,
               make_float4(za * zb.x, za * zb.y, za * zb.z, za * zb.w));

        dot.x += za * zb.x; dot.y += za * zb.y;
        dot.z += za * zb.z; dot.w += za * zb.w;
    }

    const float inv_na = 1.0f / na_s;
    float4 sim = make_float4(dot.x * inv_na / nb4.x,
                             dot.y * inv_na / nb4.y,
                             dot.z * inv_na / nb4.z,
                             dot.w * inv_na / nb4.w);
    __stcs(O + (size_t)256 * PLANE4, sim);
}

extern "C" void kernel_launch(void* const* d_in, const int* in_sizes, int n_in,
                              void* d_out, int out_size)
{
    const float* h_a = (const float*)d_in[0];
    const float* h_b = (const float*)d_in[1];
    const float* Wa  = (const float*)d_in[2];
    const float* ba  = (const float*)d_in[3];
    const float* Wb  = (const float*)d_in[4];
    const float* bb  = (const float*)d_in[5];
    float* out = (float*)d_out;

    proj_partial<<<dim3(16, 2, NKC), 256>>>(h_a, h_b, Wa, Wb);
    reduce_gelu <<<dim3(128, 2),     dim3(16, 8)>>>(ba, bb);
    interact_kernel<<<dim3(LSEQ, NB), 128>>>(out);
}